// round 1
// baseline (speedup 1.0000x reference)
#include <cuda_runtime.h>

#define HW    512
#define NIMG  16
#define TILE  64
#define TPB   256
#define EPSF  1e-8f

// Phase A: unified iterations 0..5 (6 iters), cl at halo 0
#define RA 7
#define WA 78
#define KA 6

// Phase B: unified iterations 6..20 (15 iters) + final pools, cl at halo 2
#define RB 18
#define WB 100
#define KB 15
#define CLW 68

__device__ float g_lab[2][NIMG][HW][HW];   // lab_6 intermediate (32 MB)
__device__ float g_cl [2][NIMG][HW][HW];   // cl after 6 iters   (32 MB)
__device__ float g_part[2][NIMG][64][2];   // per-tile partial sums

__device__ __forceinline__ int iclamp(int v) {
    return v < 0 ? 0 : (v > HW - 1 ? HW - 1 : v);
}

// ---------------------------------------------------------------------------
// Phase A: per 64x64 tile, fused soft-skeleton iterations 0..5 in SMEM.
// Writes cl (tile) and lab_6 (tile) to global.
// ---------------------------------------------------------------------------
__global__ void __launch_bounds__(TPB) phaseA_kernel(const float* __restrict__ x,
                                                     const int*   __restrict__ y) {
    extern __shared__ float sm[];
    float* bufA = sm;                 // WA*WA
    float* bufB = sm + WA * WA;       // WA*WA
    float* CL   = sm + 2 * WA * WA;   // TILE*TILE
    __shared__ int s_flag;

    const int tid = threadIdx.x;
    const int tx = tid & 31, ty = tid >> 5;
    const int tileIdx = blockIdx.x;
    const int img  = blockIdx.y;
    const int pipe = blockIdx.z;          // 0 = pred (x), 1 = label (one-hot of y)
    const int tY = (tileIdx >> 3) * TILE;
    const int tX = (tileIdx & 7)  * TILE;
    const int gy0 = tY - RA, gx0 = tX - RA;

    const float* __restrict__ xin = x + (size_t)img * HW * HW;
    const int*   __restrict__ yin = y + (size_t)(img >> 1) * HW * HW;
    const int cls = img & 1;

    // Load halo region with replicate (clamp) padding — exactly equivalent to
    // +inf pad for min-pool and -inf pad for max-pool.
    for (int i = ty; i < WA; i += 8) {
        int gy = iclamp(gy0 + i);
        for (int j = tx; j < WA; j += 32) {
            int gx = iclamp(gx0 + j);
            float v;
            if (pipe == 0) v = xin[gy * HW + gx];
            else           v = (yin[gy * HW + gx] == cls) ? 1.0f : 0.0f;
            bufA[i * WA + j] = v;
            bufB[i * WA + j] = 0.0f;
        }
    }
    for (int k2 = tid; k2 < TILE * TILE; k2 += TPB) CL[k2] = 0.0f;

    float* pin  = bufA;
    float* pout = bufB;

    for (int it = 0; it < KA; it++) {
        if (tid == 0) s_flag = 0;
        __syncthreads();
        const int Hh = KA - it;               // nl halo: 6,5,4,3,2,1
        const int r0 = RA - Hh, r1 = RA + TILE + Hh;
        int nz = 0;
        // nl = plus-shaped min erosion of lab
        for (int i = r0 + ty; i < r1; i += 8) {
            int gy = gy0 + i;
            if (gy < 0 || gy >= HW) continue;
            int iu = (gy > 0)      ? i - 1 : i;
            int id = (gy < HW - 1) ? i + 1 : i;
            for (int j = r0 + tx; j < r1; j += 32) {
                int gx = gx0 + j;
                if (gx < 0 || gx >= HW) continue;
                int jl = (gx > 0)      ? j - 1 : j;
                int jr = (gx < HW - 1) ? j + 1 : j;
                float v = pin[i * WA + j];
                v = fminf(v, pin[iu * WA + j]);
                v = fminf(v, pin[id * WA + j]);
                v = fminf(v, pin[i * WA + jl]);
                v = fminf(v, pin[i * WA + jr]);
                pout[i * WA + j] = v;
                nz |= (v != 0.0f);
            }
        }
        if (nz) s_flag = 1;
        __syncthreads();
        // cl += relu((1-cl) * relu(lab - maxpool3(nl)))   on the tile (halo 0)
        for (int i = RA + ty; i < RA + TILE; i += 8) {
            int gy = gy0 + i;
            int iu = (gy > 0)      ? i - 1 : i;
            int id = (gy < HW - 1) ? i + 1 : i;
            for (int j = RA + tx; j < RA + TILE; j += 32) {
                int gx = gx0 + j;
                int jl = (gx > 0)      ? j - 1 : j;
                int jr = (gx < HW - 1) ? j + 1 : j;
                float m;
                m =          pout[iu * WA + jl];
                m = fmaxf(m, pout[iu * WA + j ]);
                m = fmaxf(m, pout[iu * WA + jr]);
                m = fmaxf(m, pout[i  * WA + jl]);
                m = fmaxf(m, pout[i  * WA + j ]);
                m = fmaxf(m, pout[i  * WA + jr]);
                m = fmaxf(m, pout[id * WA + jl]);
                m = fmaxf(m, pout[id * WA + j ]);
                m = fmaxf(m, pout[id * WA + jr]);
                float lab = pin[i * WA + j];
                int   ci  = (i - RA) * TILE + (j - RA);
                float cl  = CL[ci];
                float t = fmaxf(lab - m, 0.0f);
                float u = fmaxf((1.0f - cl) * t, 0.0f);
                CL[ci] = cl + u;
            }
        }
        int f = s_flag;
        __syncthreads();
        float* tmp = pin; pin = pout; pout = tmp;
        if (!f) break;   // lab drained over halo => remaining iterations exact no-ops
    }

    // Write cl and lab_6 tiles to global
    float* __restrict__ gl = &g_lab[pipe][img][0][0];
    float* __restrict__ gc = &g_cl [pipe][img][0][0];
    for (int i = ty; i < TILE; i += 8) {
        for (int j = tx; j < TILE; j += 32) {
            gc[(tY + i) * HW + tX + j] = CL[i * TILE + j];
            gl[(tY + i) * HW + tX + j] = pin[(RA + i) * WA + RA + j];
        }
    }
}

// ---------------------------------------------------------------------------
// Phase B: iterations 6..20 (skipped entirely if lab_6 region is drained),
// then out = minpool_plus(maxpool3(cl)) and fused partial reductions.
// ---------------------------------------------------------------------------
__global__ void __launch_bounds__(TPB) phaseB_kernel(const float* __restrict__ x,
                                                     const int*   __restrict__ y) {
    extern __shared__ float sm[];
    float* bufA = sm;                 // WB*WB
    float* bufB = sm + WB * WB;       // WB*WB
    float* CL   = sm + 2 * WB * WB;   // CLW*CLW  (cl at halo 2)
    __shared__ int s_flag;
    __shared__ float s_r0[8], s_r1[8];

    const int tid = threadIdx.x;
    const int tx = tid & 31, ty = tid >> 5;
    const int tileIdx = blockIdx.x;
    const int img  = blockIdx.y;
    const int pipe = blockIdx.z;
    const int tY = (tileIdx >> 3) * TILE;
    const int tX = (tileIdx & 7)  * TILE;
    const int gy0 = tY - RB, gx0 = tX - RB;

    const float* __restrict__ gl = &g_lab[pipe][img][0][0];
    const float* __restrict__ gc = &g_cl [pipe][img][0][0];

    if (tid == 0) s_flag = 0;
    __syncthreads();

    int nz = 0;
    for (int i = ty; i < WB; i += 8) {
        int gy = iclamp(gy0 + i);
        for (int j = tx; j < WB; j += 32) {
            int gx = iclamp(gx0 + j);
            float v = gl[gy * HW + gx];
            bufA[i * WB + j] = v;
            nz |= (v != 0.0f);
        }
    }
    for (int i = ty; i < CLW; i += 8) {
        int gy = iclamp(tY - 2 + i);
        for (int j = tx; j < CLW; j += 32) {
            int gx = iclamp(tX - 2 + j);
            CL[i * CLW + j] = gc[gy * HW + gx];
        }
    }
    if (nz) s_flag = 1;
    __syncthreads();
    const int active = s_flag;

    float* pin  = bufA;
    float* pout = bufB;

    if (active) {
        for (int it = 0; it < KB; it++) {
            if (tid == 0) s_flag = 0;
            __syncthreads();
            int Hh = 17 - it; if (Hh < 3) Hh = 3;
            const int r0 = RB - Hh, r1 = RB + TILE + Hh;
            int anz = 0;
            for (int i = r0 + ty; i < r1; i += 8) {
                int gy = gy0 + i;
                if (gy < 0 || gy >= HW) continue;
                int iu = (gy > 0)      ? i - 1 : i;
                int id = (gy < HW - 1) ? i + 1 : i;
                for (int j = r0 + tx; j < r1; j += 32) {
                    int gx = gx0 + j;
                    if (gx < 0 || gx >= HW) continue;
                    int jl = (gx > 0)      ? j - 1 : j;
                    int jr = (gx < HW - 1) ? j + 1 : j;
                    float v = pin[i * WB + j];
                    v = fminf(v, pin[iu * WB + j]);
                    v = fminf(v, pin[id * WB + j]);
                    v = fminf(v, pin[i * WB + jl]);
                    v = fminf(v, pin[i * WB + jr]);
                    pout[i * WB + j] = v;
                    anz |= (v != 0.0f);
                }
            }
            if (anz) s_flag = 1;
            __syncthreads();
            // cl update at halo 2
            for (int i = RB - 2 + ty; i < RB + TILE + 2; i += 8) {
                int gy = gy0 + i;
                if (gy < 0 || gy >= HW) continue;
                int iu = (gy > 0)      ? i - 1 : i;
                int id = (gy < HW - 1) ? i + 1 : i;
                for (int j = RB - 2 + tx; j < RB + TILE + 2; j += 32) {
                    int gx = gx0 + j;
                    if (gx < 0 || gx >= HW) continue;
                    int jl = (gx > 0)      ? j - 1 : j;
                    int jr = (gx < HW - 1) ? j + 1 : j;
                    float m;
                    m =          pout[iu * WB + jl];
                    m = fmaxf(m, pout[iu * WB + j ]);
                    m = fmaxf(m, pout[iu * WB + jr]);
                    m = fmaxf(m, pout[i  * WB + jl]);
                    m = fmaxf(m, pout[i  * WB + j ]);
                    m = fmaxf(m, pout[i  * WB + jr]);
                    m = fmaxf(m, pout[id * WB + jl]);
                    m = fmaxf(m, pout[id * WB + j ]);
                    m = fmaxf(m, pout[id * WB + jr]);
                    float lab = pin[i * WB + j];
                    int   ci  = (i - (RB - 2)) * CLW + (j - (RB - 2));
                    float cl  = CL[ci];
                    float t = fmaxf(lab - m, 0.0f);
                    float u = fmaxf((1.0f - cl) * t, 0.0f);
                    CL[ci] = cl + u;
                }
            }
            int f = s_flag;
            __syncthreads();
            float* tmp = pin; pin = pout; pout = tmp;
            if (!f) break;
        }
    }

    // D = maxpool3(cl) at halo 1 (66x66), stored compactly in bufA
    float* D = bufA;
    for (int di = ty; di < 66; di += 8) {
        int gy = tY - 1 + di;
        if (gy < 0 || gy >= HW) continue;
        int ci  = di + 1;
        int ciu = (gy > 0)      ? ci - 1 : ci;
        int cid = (gy < HW - 1) ? ci + 1 : ci;
        for (int dj = tx; dj < 66; dj += 32) {
            int gx = tX - 1 + dj;
            if (gx < 0 || gx >= HW) continue;
            int cj  = dj + 1;
            int cjl = (gx > 0)      ? cj - 1 : cj;
            int cjr = (gx < HW - 1) ? cj + 1 : cj;
            float m;
            m =          CL[ciu * CLW + cjl];
            m = fmaxf(m, CL[ciu * CLW + cj ]);
            m = fmaxf(m, CL[ciu * CLW + cjr]);
            m = fmaxf(m, CL[ci  * CLW + cjl]);
            m = fmaxf(m, CL[ci  * CLW + cj ]);
            m = fmaxf(m, CL[ci  * CLW + cjr]);
            m = fmaxf(m, CL[cid * CLW + cjl]);
            m = fmaxf(m, CL[cid * CLW + cj ]);
            m = fmaxf(m, CL[cid * CLW + cjr]);
            D[di * 66 + dj] = m;
        }
    }
    __syncthreads();

    // out = plus-min of D on the tile; fuse the per-(b,c) reductions
    const float* __restrict__ xin = x + (size_t)img * HW * HW;
    const int*   __restrict__ yin = y + (size_t)(img >> 1) * HW * HW;
    const int cls = img & 1;
    float s0 = 0.0f, s1 = 0.0f;
    for (int ti2 = ty; ti2 < TILE; ti2 += 8) {
        int gy  = tY + ti2;
        int di  = ti2 + 1;
        int diu = (gy > 0)      ? di - 1 : di;
        int did = (gy < HW - 1) ? di + 1 : di;
        for (int tj = tx; tj < TILE; tj += 32) {
            int gx  = tX + tj;
            int dj  = tj + 1;
            int djl = (gx > 0)      ? dj - 1 : dj;
            int djr = (gx < HW - 1) ? dj + 1 : dj;
            float v = D[di * 66 + dj];
            v = fminf(v, D[diu * 66 + dj]);
            v = fminf(v, D[did * 66 + dj]);
            v = fminf(v, D[di * 66 + djl]);
            v = fminf(v, D[di * 66 + djr]);
            float w = (pipe == 0) ? ((yin[gy * HW + gx] == cls) ? 1.0f : 0.0f)
                                  : xin[gy * HW + gx];
            s0 += v * w;
            s1 += v;
        }
    }
    // block reduce (deterministic tree)
    for (int o = 16; o > 0; o >>= 1) {
        s0 += __shfl_down_sync(0xffffffffu, s0, o);
        s1 += __shfl_down_sync(0xffffffffu, s1, o);
    }
    if (tx == 0) { s_r0[ty] = s0; s_r1[ty] = s1; }
    __syncthreads();
    if (tid < 8) {
        s0 = s_r0[tid]; s1 = s_r1[tid];
        for (int o = 4; o > 0; o >>= 1) {
            s0 += __shfl_down_sync(0xffu, s0, o);
            s1 += __shfl_down_sync(0xffu, s1, o);
        }
        if (tid == 0) {
            g_part[pipe][img][tileIdx][0] = s0;
            g_part[pipe][img][tileIdx][1] = s1;
        }
    }
}

// ---------------------------------------------------------------------------
// Finalize: ratios, dice, mean, negate.
// ---------------------------------------------------------------------------
__global__ void finalize_kernel(float* __restrict__ out) {
    int t = threadIdx.x;   // 32 threads
    float dc = 0.0f;
    if (t < NIMG) {
        float np = 0.0f, dp = 0.0f, nl2 = 0.0f, dl = 0.0f;
        for (int k = 0; k < 64; k++) {
            np  += g_part[0][t][k][0];
            dp  += g_part[0][t][k][1];
            nl2 += g_part[1][t][k][0];
            dl  += g_part[1][t][k][1];
        }
        float a = (np  + EPSF) / (dp + EPSF);   // cl_p_2vol_l
        float b = (nl2 + EPSF) / (dl + EPSF);   // cl_l_2vol_p
        dc = 2.0f * a * b / (a + b);
    }
    for (int o = 16; o > 0; o >>= 1) dc += __shfl_down_sync(0xffffffffu, dc, o);
    if (t == 0) out[0] = -(dc * (1.0f / 16.0f));
}

// ---------------------------------------------------------------------------
extern "C" void kernel_launch(void* const* d_in, const int* in_sizes, int n_in,
                              void* d_out, int out_size) {
    const float* x = (const float*)d_in[0];
    const int*   y = (const int*)d_in[1];
    float* out = (float*)d_out;

    const int smA = (2 * WA * WA + TILE * TILE) * (int)sizeof(float);   // 65,056 B
    const int smB = (2 * WB * WB + CLW * CLW)   * (int)sizeof(float);   // 98,496 B
    cudaFuncSetAttribute(phaseA_kernel, cudaFuncAttributeMaxDynamicSharedMemorySize, smA);
    cudaFuncSetAttribute(phaseB_kernel, cudaFuncAttributeMaxDynamicSharedMemorySize, smB);

    dim3 grid(64, NIMG, 2);
    phaseA_kernel<<<grid, TPB, smA>>>(x, y);
    phaseB_kernel<<<grid, TPB, smB>>>(x, y);
    finalize_kernel<<<1, 32>>>(out);
    (void)in_sizes; (void)n_in; (void)out_size;
}

// round 3
// speedup vs baseline: 1.9005x; 1.9005x over previous
#include <cuda_runtime.h>

#define HW    512
#define NIMG  16
#define TILE  64
#define TPB   256
#define EPSF  1e-8f

// Phase A: unified iterations 0..5 (6 iters), cl at halo 0
#define RA 7
#define WA 78
#define KA 6

// Phase B: unified iterations 6..20 (15 iters) + final pools, cl at halo 2
#define RB 18
#define WB 100
#define KB 15
#define CLW 68
#define DW  66

__device__ float g_lab[2][NIMG][HW][HW];   // lab_6 intermediate (written only where nonzero)
__device__ float g_cl [2][NIMG][HW][HW];   // cl after 6 iters
__device__ int   g_flag[2][NIMG][64];      // per-tile: lab_6 tile has nonzeros
__device__ float g_part[2][NIMG][64][2];   // per-tile partial sums

__device__ __forceinline__ int iclamp(int v) {
    return v < 0 ? 0 : (v > HW - 1 ? HW - 1 : v);
}

// ---------------------------------------------------------------------------
// Phase A: per 64x64 tile, fused soft-skeleton iterations 0..5 in SMEM.
// No per-cell boundary checks: clamp-loaded buffer makes the free-running
// min-erosion exact; a cheap re-clamp of the virtual band (edge tiles only)
// makes the max-pool exact.
// ---------------------------------------------------------------------------
__global__ void __launch_bounds__(TPB) phaseA_kernel(const float* __restrict__ x,
                                                     const int*   __restrict__ y) {
    extern __shared__ float sm[];
    float* bufA = sm;                 // WA*WA
    float* bufB = sm + WA * WA;       // WA*WA
    float* CL   = sm + 2 * WA * WA;   // TILE*TILE

    const int tid = threadIdx.x;
    const int tx = tid & 31, ty = tid >> 5;
    const int tileIdx = blockIdx.x;
    const int img  = blockIdx.y;
    const int pipe = blockIdx.z;          // 0 = pred (x), 1 = label (one-hot of y)
    const int tY = (tileIdx >> 3) * TILE;
    const int tX = (tileIdx & 7)  * TILE;
    const int gy0 = tY - RA, gx0 = tX - RA;
    const bool edge = (tY == 0) || (tX == 0) || (tY == HW - TILE) || (tX == HW - TILE);
    const int vTop = (tY == 0)         ? 1 : 0;
    const int vBot = (tY == HW - TILE) ? 1 : 0;
    const int vL   = (tX == 0)         ? 1 : 0;
    const int vR   = (tX == HW - TILE) ? 1 : 0;

    const float* __restrict__ xin = x + (size_t)img * HW * HW;
    const int*   __restrict__ yin = y + (size_t)(img >> 1) * HW * HW;
    const int cls = img & 1;

    // Load halo region (clamped indexing == replicate padding).
    if (!edge) {
        if (pipe == 0) {
            for (int i = ty; i < WA; i += 8) {
                const float* src = xin + (gy0 + i) * HW + gx0;
                float* dst = bufA + i * WA;
                for (int j = tx; j < WA; j += 32) dst[j] = src[j];
            }
        } else {
            for (int i = ty; i < WA; i += 8) {
                const int* src = yin + (gy0 + i) * HW + gx0;
                float* dst = bufA + i * WA;
                for (int j = tx; j < WA; j += 32) dst[j] = (src[j] == cls) ? 1.0f : 0.0f;
            }
        }
    } else {
        for (int i = ty; i < WA; i += 8) {
            const int gy = iclamp(gy0 + i);
            float* dst = bufA + i * WA;
            for (int j = tx; j < WA; j += 32) {
                const int gx = iclamp(gx0 + j);
                float v;
                if (pipe == 0) v = xin[gy * HW + gx];
                else           v = (yin[gy * HW + gx] == cls) ? 1.0f : 0.0f;
                dst[j] = v;
            }
        }
    }
    for (int k = tid; k < TILE * TILE; k += TPB) CL[k] = 0.0f;
    __syncthreads();

    float* pin  = bufA;
    float* pout = bufB;

    for (int it = 0; it < KA; it++) {
        const int Hh = KA - it;               // nl halo: 6,5,4,3,2,1
        const int r0 = RA - Hh, r1 = RA + TILE + Hh;
        int nz = 0;
        // nl = plus-shaped min erosion of lab (no checks)
        for (int i = r0 + ty; i < r1; i += 8) {
            const float* rc = pin + i * WA;
            float* ro = pout + i * WA;
            for (int j = r0 + tx; j < r1; j += 32) {
                float v = fminf(fminf(rc[j - 1], rc[j]), rc[j + 1]);
                v = fminf(v, fminf(rc[j - WA], rc[j + WA]));
                ro[j] = v;
                nz |= (v != 0.0f);
            }
        }
        const int any = __syncthreads_or(nz);

        // Re-clamp the virtual band of pout (edge tiles only) so the maxpool
        // and next erosion see exact replicate padding.
        if (edge) {
            if (vTop) for (int i = r0 + ty; i < RA; i += 8) {
                float* d = pout + i * WA; const float* s = pout + RA * WA;
                for (int j = r0 + tx; j < r1; j += 32) d[j] = s[j];
            }
            if (vBot) for (int i = RA + TILE + ty; i < r1; i += 8) {
                float* d = pout + i * WA; const float* s = pout + (RA + TILE - 1) * WA;
                for (int j = r0 + tx; j < r1; j += 32) d[j] = s[j];
            }
            __syncthreads();
            if (vL) for (int i = r0 + ty; i < r1; i += 8) {
                const float s = pout[i * WA + RA];
                for (int j = r0 + tx; j < RA; j += 32) pout[i * WA + j] = s;
            }
            if (vR) for (int i = r0 + ty; i < r1; i += 8) {
                const float s = pout[i * WA + RA + TILE - 1];
                for (int j = RA + TILE + tx; j < r1; j += 32) pout[i * WA + j] = s;
            }
            __syncthreads();
        }

        // cl += relu((1-cl)*relu(lab - maxpool3(nl))) on the tile.
        // Banded: warp ty owns 8 consecutive rows; vertical 3-tap sliding max.
        {
            const int rbase = RA + ty * 8;
            #pragma unroll
            for (int c = 0; c < 2; c++) {
                const int jj = RA + tx + c * 32;
                const float* p = pout + (rbase - 1) * WA + jj;
                float h0 = fmaxf(fmaxf(p[-1], p[0]), p[1]); p += WA;
                float h1 = fmaxf(fmaxf(p[-1], p[0]), p[1]); p += WA;
                const float* lp = pin + rbase * WA + jj;
                float* cp = CL + (ty * 8) * TILE + tx + c * 32;
                #pragma unroll
                for (int r = 0; r < 8; r++) {
                    const float h2 = fmaxf(fmaxf(p[-1], p[0]), p[1]); p += WA;
                    const float m = fmaxf(fmaxf(h0, h1), h2);
                    const float lab = lp[0]; lp += WA;
                    const float t = lab - m;
                    if (t > 0.0f) {
                        const float cl = cp[0];
                        cp[0] = cl + fmaxf((1.0f - cl) * t, 0.0f);
                    }
                    cp += TILE;
                    h0 = h1; h1 = h2;
                }
            }
        }
        __syncthreads();
        float* tmp = pin; pin = pout; pout = tmp;
        if (!any) break;   // drained over needed halo => remaining iters exact no-ops
    }

    // Store cl always; lab_6 only if the tile has nonzeros; flag always.
    float* __restrict__ gl = &g_lab[pipe][img][0][0];
    float* __restrict__ gc = &g_cl [pipe][img][0][0];
    int tnz = 0;
    for (int i = ty; i < TILE; i += 8) {
        const float* lr = pin + (RA + i) * WA + RA;
        const float* cr = CL + i * TILE;
        float* go = gc + (tY + i) * HW + tX;
        for (int j = tx; j < TILE; j += 32) {
            go[j] = cr[j];
            tnz |= (lr[j] != 0.0f);
        }
    }
    tnz = __syncthreads_or(tnz);
    if (tnz) {
        for (int i = ty; i < TILE; i += 8) {
            const float* lr = pin + (RA + i) * WA + RA;
            float* go = gl + (tY + i) * HW + tX;
            for (int j = tx; j < TILE; j += 32) go[j] = lr[j];
        }
    }
    if (tid == 0) g_flag[pipe][img][tileIdx] = tnz;
}

// ---------------------------------------------------------------------------
// Phase B: if the 3x3 covering flags are all zero (expected), skip straight to
// the final pools + reduction. Otherwise run iterations 6..20 (checked path).
// ---------------------------------------------------------------------------
__global__ void __launch_bounds__(TPB) phaseB_kernel(const float* __restrict__ x,
                                                     const int*   __restrict__ y) {
    extern __shared__ float sm[];
    float* bufA = sm;                 // WB*WB (lab ping; reused for D 66x66)
    float* bufB = sm + WB * WB;       // WB*WB (lab pong; reused for Hb 68x66)
    float* CLB  = sm + 2 * WB * WB;   // CLW*CLW (cl at halo 2)
    __shared__ float s_r0[8], s_r1[8];
    __shared__ int s_flags[9];

    const int tid = threadIdx.x;
    const int tx = tid & 31, ty = tid >> 5;
    const int tileIdx = blockIdx.x;
    const int img  = blockIdx.y;
    const int pipe = blockIdx.z;
    const int tr = tileIdx >> 3, tc = tileIdx & 7;
    const int tY = tr * TILE, tX = tc * TILE;
    const int gy0 = tY - RB, gx0 = tX - RB;
    const bool edge = (tY == 0) || (tX == 0) || (tY == HW - TILE) || (tX == HW - TILE);

    const float* __restrict__ gl = &g_lab[pipe][img][0][0];
    const float* __restrict__ gc = &g_cl [pipe][img][0][0];

    if (tid < 9) {
        const int rr = tr + tid / 3 - 1, cc = tc + tid % 3 - 1;
        int f = 0;
        if (rr >= 0 && rr < 8 && cc >= 0 && cc < 8) f = g_flag[pipe][img][rr * 8 + cc];
        s_flags[tid] = f;
    }

    // Load cl at halo 2 (always needed).
    for (int i = ty; i < CLW; i += 8) {
        const int gy = iclamp(tY - 2 + i);
        float* d = CLB + i * CLW;
        for (int j = tx; j < CLW; j += 32) d[j] = gc[gy * HW + iclamp(tX - 2 + j)];
    }
    __syncthreads();

    int anyLab = 0;
    #pragma unroll
    for (int k = 0; k < 9; k++) anyLab |= s_flags[k];

    if (anyLab) {
        // -------- slow path (exact, flag-gated loads; never taken when drained)
        for (int i = ty; i < WB; i += 8) {
            const int gy = iclamp(gy0 + i);
            const int fr = (gy >> 6) - (tr - 1);
            for (int j = tx; j < WB; j += 32) {
                const int gx = iclamp(gx0 + j);
                const int fc = (gx >> 6) - (tc - 1);
                bufA[i * WB + j] = s_flags[fr * 3 + fc] ? gl[gy * HW + gx] : 0.0f;
            }
        }
        __syncthreads();

        float* pin  = bufA;
        float* pout = bufB;
        for (int it = 0; it < KB; it++) {
            int Hh = 17 - it; if (Hh < 3) Hh = 3;
            const int r0 = RB - Hh, r1 = RB + TILE + Hh;
            int nz = 0;
            for (int i = r0 + ty; i < r1; i += 8) {
                const int gy = gy0 + i;
                if (gy < 0 || gy >= HW) continue;
                const int iu = (gy > 0)      ? i - 1 : i;
                const int id = (gy < HW - 1) ? i + 1 : i;
                for (int j = r0 + tx; j < r1; j += 32) {
                    const int gx = gx0 + j;
                    if (gx < 0 || gx >= HW) continue;
                    const int jl = (gx > 0)      ? j - 1 : j;
                    const int jr = (gx < HW - 1) ? j + 1 : j;
                    float v = pin[i * WB + j];
                    v = fminf(v, pin[iu * WB + j]);
                    v = fminf(v, pin[id * WB + j]);
                    v = fminf(v, pin[i * WB + jl]);
                    v = fminf(v, pin[i * WB + jr]);
                    pout[i * WB + j] = v;
                    nz |= (v != 0.0f);
                }
            }
            const int any = __syncthreads_or(nz);
            for (int i = RB - 2 + ty; i < RB + TILE + 2; i += 8) {
                const int gy = gy0 + i;
                if (gy < 0 || gy >= HW) continue;
                const int iu = (gy > 0)      ? i - 1 : i;
                const int id = (gy < HW - 1) ? i + 1 : i;
                for (int j = RB - 2 + tx; j < RB + TILE + 2; j += 32) {
                    const int gx = gx0 + j;
                    if (gx < 0 || gx >= HW) continue;
                    const int jl = (gx > 0)      ? j - 1 : j;
                    const int jr = (gx < HW - 1) ? j + 1 : j;
                    float m;
                    m =          pout[iu * WB + jl];
                    m = fmaxf(m, pout[iu * WB + j ]);
                    m = fmaxf(m, pout[iu * WB + jr]);
                    m = fmaxf(m, pout[i  * WB + jl]);
                    m = fmaxf(m, pout[i  * WB + j ]);
                    m = fmaxf(m, pout[i  * WB + jr]);
                    m = fmaxf(m, pout[id * WB + jl]);
                    m = fmaxf(m, pout[id * WB + j ]);
                    m = fmaxf(m, pout[id * WB + jr]);
                    const float lab = pin[i * WB + j];
                    const int ci = (i - (RB - 2)) * CLW + (j - (RB - 2));
                    const float cl = CLB[ci];
                    const float t = fmaxf(lab - m, 0.0f);
                    CLB[ci] = cl + fmaxf((1.0f - cl) * t, 0.0f);
                }
            }
            __syncthreads();
            float* tmp = pin; pin = pout; pout = tmp;
            if (!any) break;
        }
    }

    // Re-clamp CLB virtual band (edge tiles) so the pools read exact replicate.
    if (edge) {
        if (tY == 0)
            for (int k = tid; k < 2 * CLW; k += TPB) CLB[(k / CLW) * CLW + k % CLW] = CLB[2 * CLW + k % CLW];
        if (tY == HW - TILE)
            for (int k = tid; k < 2 * CLW; k += TPB) CLB[(66 + k / CLW) * CLW + k % CLW] = CLB[65 * CLW + k % CLW];
        __syncthreads();
        if (tX == 0)
            for (int k = tid; k < 2 * CLW; k += TPB) CLB[(k >> 1) * CLW + (k & 1)] = CLB[(k >> 1) * CLW + 2];
        if (tX == HW - TILE)
            for (int k = tid; k < 2 * CLW; k += TPB) CLB[(k >> 1) * CLW + 66 + (k & 1)] = CLB[(k >> 1) * CLW + 65];
        __syncthreads();
    }

    // Separable maxpool3: Hb = hmax3 rows, D = vmax3(Hb).
    float* Hb = bufB;   // CLW x DW
    for (int c = ty; c < CLW; c += 8) {
        const float* r = CLB + c * CLW;
        float* hb = Hb + c * DW;
        for (int e = tx; e < DW; e += 32)
            hb[e] = fmaxf(fmaxf(r[e], r[e + 1]), r[e + 2]);
    }
    __syncthreads();
    float* D = bufA;    // DW x DW
    for (int d = ty; d < DW; d += 8) {
        const float* h = Hb + d * DW;
        float* dd = D + d * DW;
        for (int e = tx; e < DW; e += 32)
            dd[e] = fmaxf(fmaxf(h[e], h[e + DW]), h[e + 2 * DW]);
    }
    __syncthreads();
    // Re-clamp D virtual rim (edge tiles) for the final plus-min.
    if (edge) {
        if (tY == 0)          for (int e = tid; e < DW; e += TPB) D[e]           = D[DW + e];
        if (tY == HW - TILE)  for (int e = tid; e < DW; e += TPB) D[65 * DW + e] = D[64 * DW + e];
        __syncthreads();
        if (tX == 0)          for (int d = tid; d < DW; d += TPB) D[d * DW]      = D[d * DW + 1];
        if (tX == HW - TILE)  for (int d = tid; d < DW; d += TPB) D[d * DW + 65] = D[d * DW + 64];
        __syncthreads();
    }

    // out = plus-min of D on the tile; fuse the per-(b,c) reductions.
    const float* __restrict__ xin = x + (size_t)img * HW * HW;
    const int*   __restrict__ yin = y + (size_t)(img >> 1) * HW * HW;
    const int cls = img & 1;
    float s0 = 0.0f, s1 = 0.0f;
    for (int i2 = ty; i2 < TILE; i2 += 8) {
        const int gy = tY + i2;
        const float* dc = D + (i2 + 1) * DW;
        for (int j2 = tx; j2 < TILE; j2 += 32) {
            const int e = j2 + 1;
            float v = fminf(fminf(dc[e - 1], dc[e]), dc[e + 1]);
            v = fminf(v, fminf(dc[e - DW], dc[e + DW]));
            const float w = (pipe == 0) ? ((yin[gy * HW + tX + j2] == cls) ? 1.0f : 0.0f)
                                        : xin[gy * HW + tX + j2];
            s0 += v * w;
            s1 += v;
        }
    }
    for (int o = 16; o > 0; o >>= 1) {
        s0 += __shfl_down_sync(0xffffffffu, s0, o);
        s1 += __shfl_down_sync(0xffffffffu, s1, o);
    }
    if (tx == 0) { s_r0[ty] = s0; s_r1[ty] = s1; }
    __syncthreads();
    if (tid < 8) {
        s0 = s_r0[tid]; s1 = s_r1[tid];
        for (int o = 4; o > 0; o >>= 1) {
            s0 += __shfl_down_sync(0xffu, s0, o);
            s1 += __shfl_down_sync(0xffu, s1, o);
        }
        if (tid == 0) {
            g_part[pipe][img][tileIdx][0] = s0;
            g_part[pipe][img][tileIdx][1] = s1;
        }
    }
}

// ---------------------------------------------------------------------------
__global__ void finalize_kernel(float* __restrict__ out) {
    const int t = threadIdx.x;   // 32 threads
    float dc = 0.0f;
    if (t < NIMG) {
        float np = 0.0f, dp = 0.0f, nl2 = 0.0f, dl = 0.0f;
        for (int k = 0; k < 64; k++) {
            np  += g_part[0][t][k][0];
            dp  += g_part[0][t][k][1];
            nl2 += g_part[1][t][k][0];
            dl  += g_part[1][t][k][1];
        }
        const float a = (np  + EPSF) / (dp + EPSF);
        const float b = (nl2 + EPSF) / (dl + EPSF);
        dc = 2.0f * a * b / (a + b);
    }
    for (int o = 16; o > 0; o >>= 1) dc += __shfl_down_sync(0xffffffffu, dc, o);
    if (t == 0) out[0] = -(dc * (1.0f / 16.0f));
}

// ---------------------------------------------------------------------------
extern "C" void kernel_launch(void* const* d_in, const int* in_sizes, int n_in,
                              void* d_out, int out_size) {
    const float* x = (const float*)d_in[0];
    const int*   y = (const int*)d_in[1];
    float* out = (float*)d_out;

    const int smA = (2 * WA * WA + TILE * TILE) * (int)sizeof(float);   // 65,056 B
    const int smB = (2 * WB * WB + CLW * CLW)   * (int)sizeof(float);   // 98,496 B
    cudaFuncSetAttribute(phaseA_kernel, cudaFuncAttributeMaxDynamicSharedMemorySize, smA);
    cudaFuncSetAttribute(phaseB_kernel, cudaFuncAttributeMaxDynamicSharedMemorySize, smB);

    dim3 grid(64, NIMG, 2);
    phaseA_kernel<<<grid, TPB, smA>>>(x, y);
    phaseB_kernel<<<grid, TPB, smB>>>(x, y);
    finalize_kernel<<<1, 32>>>(out);
    (void)in_sizes; (void)n_in; (void)out_size;
}

// round 4
// speedup vs baseline: 2.9773x; 1.5666x over previous
#include <cuda_runtime.h>

#define HW    512
#define NIMG  16
#define TILE  64
#define TPB   256
#define EPSF  1e-8f

// Phase A: unified iterations 0..5 (6 iters), cl at halo 0
#define RA 7
#define WA 78
#define KA 6

// Phase B: unified iterations 6..20 (15 iters) + final pools, cl at halo 2
#define RB 18
#define WB 100
#define KB 15
#define CLW 68
#define DW  66

__device__ float g_lab[2][NIMG][HW][HW];   // lab_6 intermediate (written only where nonzero)
__device__ float g_cl [2][NIMG][HW][HW];   // cl after 6 iters
__device__ int   g_flag[2][NIMG][64];      // per-tile: lab_6 tile has nonzeros
__device__ float g_part[2][NIMG][64][2];   // per-tile partial sums

__device__ __forceinline__ int iclamp(int v) {
    return v < 0 ? 0 : (v > HW - 1 ? HW - 1 : v);
}

// ---------------------------------------------------------------------------
// Phase A: per 64x64 tile, fused soft-skeleton iterations 0..5 in SMEM.
// cl lives in registers (warp-banded); smem holds only the two lab buffers.
// ---------------------------------------------------------------------------
__global__ void __launch_bounds__(TPB, 4) phaseA_kernel(const float* __restrict__ x,
                                                        const int*   __restrict__ y) {
    extern __shared__ float sm[];
    float* bufA = sm;                 // WA*WA
    float* bufB = sm + WA * WA;       // WA*WA

    const int tid = threadIdx.x;
    const int tx = tid & 31, ty = tid >> 5;
    const int tileIdx = blockIdx.x;
    const int img  = blockIdx.y;
    const int pipe = blockIdx.z;          // 0 = pred (x), 1 = label (one-hot of y)
    const int tY = (tileIdx >> 3) * TILE;
    const int tX = (tileIdx & 7)  * TILE;
    const int gy0 = tY - RA, gx0 = tX - RA;
    const bool edge = (tY == 0) || (tX == 0) || (tY == HW - TILE) || (tX == HW - TILE);
    const int vTop = (tY == 0)         ? 1 : 0;
    const int vBot = (tY == HW - TILE) ? 1 : 0;
    const int vL   = (tX == 0)         ? 1 : 0;
    const int vR   = (tX == HW - TILE) ? 1 : 0;

    const float* __restrict__ xin = x + (size_t)img * HW * HW;
    const int*   __restrict__ yin = y + (size_t)(img >> 1) * HW * HW;
    const int cls = img & 1;

    // Load halo region (clamped indexing == replicate padding).
    if (!edge) {
        if (pipe == 0) {
            for (int i = ty; i < WA; i += 8) {
                const float* src = xin + (gy0 + i) * HW + gx0;
                float* dst = bufA + i * WA;
                for (int j = tx; j < WA; j += 32) dst[j] = src[j];
            }
        } else {
            for (int i = ty; i < WA; i += 8) {
                const int* src = yin + (gy0 + i) * HW + gx0;
                float* dst = bufA + i * WA;
                for (int j = tx; j < WA; j += 32) dst[j] = (src[j] == cls) ? 1.0f : 0.0f;
            }
        }
    } else {
        for (int i = ty; i < WA; i += 8) {
            const int gy = iclamp(gy0 + i);
            float* dst = bufA + i * WA;
            for (int j = tx; j < WA; j += 32) {
                const int gx = iclamp(gx0 + j);
                float v;
                if (pipe == 0) v = xin[gy * HW + gx];
                else           v = (yin[gy * HW + gx] == cls) ? 1.0f : 0.0f;
                dst[j] = v;
            }
        }
    }

    // cl in registers: warp ty owns rows ty*8..ty*8+7; thread cols tx, tx+32.
    float clr[2][8];
    #pragma unroll
    for (int c = 0; c < 2; c++)
        #pragma unroll
        for (int r = 0; r < 8; r++) clr[c][r] = 0.0f;

    __syncthreads();

    float* pin  = bufA;
    float* pout = bufB;

    for (int it = 0; it < KA; it++) {
        const int Hh = KA - it;               // nl halo: 6,5,4,3,2,1
        const int r0 = RA - Hh, r1 = RA + TILE + Hh;
        int nz = 0;
        // nl = plus-shaped min erosion of lab (no checks)
        for (int i = r0 + ty; i < r1; i += 8) {
            const float* rc = pin + i * WA;
            float* ro = pout + i * WA;
            for (int j = r0 + tx; j < r1; j += 32) {
                float v = fminf(fminf(rc[j - 1], rc[j]), rc[j + 1]);
                v = fminf(v, fminf(rc[j - WA], rc[j + WA]));
                ro[j] = v;
                nz |= (v != 0.0f);
            }
        }
        const int any = __syncthreads_or(nz);

        // Re-clamp the virtual band of pout (edge tiles only) so the maxpool
        // and next erosion see exact replicate padding.
        if (edge) {
            if (vTop) for (int i = r0 + ty; i < RA; i += 8) {
                float* d = pout + i * WA; const float* s = pout + RA * WA;
                for (int j = r0 + tx; j < r1; j += 32) d[j] = s[j];
            }
            if (vBot) for (int i = RA + TILE + ty; i < r1; i += 8) {
                float* d = pout + i * WA; const float* s = pout + (RA + TILE - 1) * WA;
                for (int j = r0 + tx; j < r1; j += 32) d[j] = s[j];
            }
            __syncthreads();
            if (vL) for (int i = r0 + ty; i < r1; i += 8) {
                const float s = pout[i * WA + RA];
                for (int j = r0 + tx; j < RA; j += 32) pout[i * WA + j] = s;
            }
            if (vR) for (int i = r0 + ty; i < r1; i += 8) {
                const float s = pout[i * WA + RA + TILE - 1];
                for (int j = RA + TILE + tx; j < r1; j += 32) pout[i * WA + j] = s;
            }
            __syncthreads();
        }

        // cl += relu((1-cl)*relu(lab - maxpool3(nl))) — skip whole warp band
        // when lab is zero there (exact: lab=0 => t<=0 since m>=0).
        {
            const int rbase = RA + ty * 8;
            float labv[2][8];
            int lz = 0;
            #pragma unroll
            for (int c = 0; c < 2; c++) {
                const float* lp = pin + rbase * WA + RA + tx + c * 32;
                #pragma unroll
                for (int r = 0; r < 8; r++) {
                    labv[c][r] = lp[r * WA];
                    lz |= (labv[c][r] != 0.0f);
                }
            }
            if (__ballot_sync(0xffffffffu, lz)) {
                #pragma unroll
                for (int c = 0; c < 2; c++) {
                    const int jj = RA + tx + c * 32;
                    const float* p = pout + (rbase - 1) * WA + jj;
                    float h0 = fmaxf(fmaxf(p[-1], p[0]), p[1]); p += WA;
                    float h1 = fmaxf(fmaxf(p[-1], p[0]), p[1]); p += WA;
                    #pragma unroll
                    for (int r = 0; r < 8; r++) {
                        const float h2 = fmaxf(fmaxf(p[-1], p[0]), p[1]); p += WA;
                        const float m = fmaxf(fmaxf(h0, h1), h2);
                        const float t = labv[c][r] - m;
                        if (t > 0.0f) {
                            const float cl = clr[c][r];
                            clr[c][r] = cl + fmaxf((1.0f - cl) * t, 0.0f);
                        }
                        h0 = h1; h1 = h2;
                    }
                }
            }
        }
        __syncthreads();
        float* tmp = pin; pin = pout; pout = tmp;
        if (!any) break;   // drained over needed halo => remaining iters exact no-ops
    }

    // Store cl (from registers) always; lab_6 only if tile has nonzeros; flag.
    float* __restrict__ gl = &g_lab[pipe][img][0][0];
    float* __restrict__ gc = &g_cl [pipe][img][0][0];
    int tnz = 0;
    #pragma unroll
    for (int r = 0; r < 8; r++) {
        const int row = ty * 8 + r;
        float* go = gc + (tY + row) * HW + tX;
        const float* lr = pin + (RA + row) * WA + RA;
        #pragma unroll
        for (int c = 0; c < 2; c++) {
            go[tx + c * 32] = clr[c][r];
            tnz |= (lr[tx + c * 32] != 0.0f);
        }
    }
    tnz = __syncthreads_or(tnz);
    if (tnz) {
        #pragma unroll
        for (int r = 0; r < 8; r++) {
            const int row = ty * 8 + r;
            const float* lr = pin + (RA + row) * WA + RA;
            float* go = gl + (tY + row) * HW + tX;
            go[tx]      = lr[tx];
            go[tx + 32] = lr[tx + 32];
        }
    }
    if (tid == 0) g_flag[pipe][img][tileIdx] = tnz;
}

// ---------------------------------------------------------------------------
// fastB: handles tiles whose 3x3 covering flags are ALL zero (lab_6 drained):
// final pools + fused reduction only. Small static smem -> 6 CTA/SM.
// ---------------------------------------------------------------------------
__global__ void __launch_bounds__(TPB) fastB_kernel(const float* __restrict__ x,
                                                    const int*   __restrict__ y) {
    __shared__ float CLB[CLW * CLW];   // cl at halo 2; later reused for D (66x66, stride DW)
    __shared__ float HB[CLW * DW];     // horizontal max rows
    __shared__ float s_r0[8], s_r1[8];
    __shared__ int s_any;

    const int tid = threadIdx.x;
    const int tx = tid & 31, ty = tid >> 5;
    const int tileIdx = blockIdx.x;
    const int img  = blockIdx.y;
    const int pipe = blockIdx.z;
    const int tr = tileIdx >> 3, tc = tileIdx & 7;
    const int tY = tr * TILE, tX = tc * TILE;
    const bool edge = (tY == 0) || (tX == 0) || (tY == HW - TILE) || (tX == HW - TILE);

    if (tid == 0) {
        int a = 0;
        #pragma unroll
        for (int dr = -1; dr <= 1; dr++)
            #pragma unroll
            for (int dc2 = -1; dc2 <= 1; dc2++) {
                const int rr = tr + dr, cc = tc + dc2;
                if (rr >= 0 && rr < 8 && cc >= 0 && cc < 8)
                    a |= g_flag[pipe][img][rr * 8 + cc];
            }
        s_any = a;
    }
    __syncthreads();
    if (s_any) return;   // slowB owns this tile

    const float* __restrict__ gc = &g_cl[pipe][img][0][0];
    for (int i = ty; i < CLW; i += 8) {
        const int gy = iclamp(tY - 2 + i);
        float* d = CLB + i * CLW;
        for (int j = tx; j < CLW; j += 32) d[j] = gc[gy * HW + iclamp(tX - 2 + j)];
    }
    __syncthreads();

    // Re-clamp CLB virtual band (edge tiles) so the pools read exact replicate.
    if (edge) {
        if (tY == 0)
            for (int k = tid; k < 2 * CLW; k += TPB) CLB[(k / CLW) * CLW + k % CLW] = CLB[2 * CLW + k % CLW];
        if (tY == HW - TILE)
            for (int k = tid; k < 2 * CLW; k += TPB) CLB[(66 + k / CLW) * CLW + k % CLW] = CLB[65 * CLW + k % CLW];
        __syncthreads();
        if (tX == 0)
            for (int k = tid; k < 2 * CLW; k += TPB) CLB[(k >> 1) * CLW + (k & 1)] = CLB[(k >> 1) * CLW + 2];
        if (tX == HW - TILE)
            for (int k = tid; k < 2 * CLW; k += TPB) CLB[(k >> 1) * CLW + 66 + (k & 1)] = CLB[(k >> 1) * CLW + 65];
        __syncthreads();
    }

    // Separable maxpool3: HB = hmax3 rows
    for (int c = ty; c < CLW; c += 8) {
        const float* r = CLB + c * CLW;
        float* hb = HB + c * DW;
        for (int e = tx; e < DW; e += 32)
            hb[e] = fmaxf(fmaxf(r[e], r[e + 1]), r[e + 2]);
    }
    __syncthreads();
    // D = vmax3(HB), written into CLB (free now), stride DW
    float* D = CLB;
    for (int d = ty; d < DW; d += 8) {
        const float* h = HB + d * DW;
        float* dd = D + d * DW;
        for (int e = tx; e < DW; e += 32)
            dd[e] = fmaxf(fmaxf(h[e], h[e + DW]), h[e + 2 * DW]);
    }
    __syncthreads();
    if (edge) {
        if (tY == 0)          for (int e = tid; e < DW; e += TPB) D[e]           = D[DW + e];
        if (tY == HW - TILE)  for (int e = tid; e < DW; e += TPB) D[65 * DW + e] = D[64 * DW + e];
        __syncthreads();
        if (tX == 0)          for (int d = tid; d < DW; d += TPB) D[d * DW]      = D[d * DW + 1];
        if (tX == HW - TILE)  for (int d = tid; d < DW; d += TPB) D[d * DW + 65] = D[d * DW + 64];
        __syncthreads();
    }

    // out = plus-min of D on the tile; fuse the per-(b,c) reductions.
    const float* __restrict__ xin = x + (size_t)img * HW * HW;
    const int*   __restrict__ yin = y + (size_t)(img >> 1) * HW * HW;
    const int cls = img & 1;
    float s0 = 0.0f, s1 = 0.0f;
    for (int i2 = ty; i2 < TILE; i2 += 8) {
        const int gy = tY + i2;
        const float* dc = D + (i2 + 1) * DW;
        for (int j2 = tx; j2 < TILE; j2 += 32) {
            const int e = j2 + 1;
            float v = fminf(fminf(dc[e - 1], dc[e]), dc[e + 1]);
            v = fminf(v, fminf(dc[e - DW], dc[e + DW]));
            const float w = (pipe == 0) ? ((yin[gy * HW + tX + j2] == cls) ? 1.0f : 0.0f)
                                        : xin[gy * HW + tX + j2];
            s0 += v * w;
            s1 += v;
        }
    }
    for (int o = 16; o > 0; o >>= 1) {
        s0 += __shfl_down_sync(0xffffffffu, s0, o);
        s1 += __shfl_down_sync(0xffffffffu, s1, o);
    }
    if (tx == 0) { s_r0[ty] = s0; s_r1[ty] = s1; }
    __syncthreads();
    if (tid < 8) {
        s0 = s_r0[tid]; s1 = s_r1[tid];
        for (int o = 4; o > 0; o >>= 1) {
            s0 += __shfl_down_sync(0xffu, s0, o);
            s1 += __shfl_down_sync(0xffu, s1, o);
        }
        if (tid == 0) {
            g_part[pipe][img][tileIdx][0] = s0;
            g_part[pipe][img][tileIdx][1] = s1;
        }
    }
}

// ---------------------------------------------------------------------------
// slowB: handles tiles with any covering flag set: iterations 6..20 + pools +
// reduction. Exits immediately otherwise (expected for all tiles).
// ---------------------------------------------------------------------------
__global__ void __launch_bounds__(TPB) slowB_kernel(const float* __restrict__ x,
                                                    const int*   __restrict__ y) {
    extern __shared__ float sm[];
    float* bufA = sm;                 // WB*WB (lab ping; reused for D 66x66)
    float* bufB = sm + WB * WB;       // WB*WB (lab pong; reused for Hb 68x66)
    float* CLB  = sm + 2 * WB * WB;   // CLW*CLW (cl at halo 2)
    __shared__ float s_r0[8], s_r1[8];
    __shared__ int s_flags[9];

    const int tid = threadIdx.x;
    const int tx = tid & 31, ty = tid >> 5;
    const int tileIdx = blockIdx.x;
    const int img  = blockIdx.y;
    const int pipe = blockIdx.z;
    const int tr = tileIdx >> 3, tc = tileIdx & 7;
    const int tY = tr * TILE, tX = tc * TILE;
    const int gy0 = tY - RB, gx0 = tX - RB;
    const bool edge = (tY == 0) || (tX == 0) || (tY == HW - TILE) || (tX == HW - TILE);

    if (tid < 9) {
        const int rr = tr + tid / 3 - 1, cc = tc + tid % 3 - 1;
        int f = 0;
        if (rr >= 0 && rr < 8 && cc >= 0 && cc < 8) f = g_flag[pipe][img][rr * 8 + cc];
        s_flags[tid] = f;
    }
    __syncthreads();
    int anyLab = 0;
    #pragma unroll
    for (int k = 0; k < 9; k++) anyLab |= s_flags[k];
    if (!anyLab) return;   // fastB owns this tile

    const float* __restrict__ gl = &g_lab[pipe][img][0][0];
    const float* __restrict__ gc = &g_cl [pipe][img][0][0];

    // Load cl at halo 2.
    for (int i = ty; i < CLW; i += 8) {
        const int gy = iclamp(tY - 2 + i);
        float* d = CLB + i * CLW;
        for (int j = tx; j < CLW; j += 32) d[j] = gc[gy * HW + iclamp(tX - 2 + j)];
    }
    // Load lab_6 halo, flag-gated.
    for (int i = ty; i < WB; i += 8) {
        const int gy = iclamp(gy0 + i);
        const int fr = (gy >> 6) - (tr - 1);
        for (int j = tx; j < WB; j += 32) {
            const int gx = iclamp(gx0 + j);
            const int fc = (gx >> 6) - (tc - 1);
            bufA[i * WB + j] = s_flags[fr * 3 + fc] ? gl[gy * HW + gx] : 0.0f;
        }
    }
    __syncthreads();

    float* pin  = bufA;
    float* pout = bufB;
    for (int it = 0; it < KB; it++) {
        int Hh = 17 - it; if (Hh < 3) Hh = 3;
        const int r0 = RB - Hh, r1 = RB + TILE + Hh;
        int nz = 0;
        for (int i = r0 + ty; i < r1; i += 8) {
            const int gy = gy0 + i;
            if (gy < 0 || gy >= HW) continue;
            const int iu = (gy > 0)      ? i - 1 : i;
            const int id = (gy < HW - 1) ? i + 1 : i;
            for (int j = r0 + tx; j < r1; j += 32) {
                const int gx = gx0 + j;
                if (gx < 0 || gx >= HW) continue;
                const int jl = (gx > 0)      ? j - 1 : j;
                const int jr = (gx < HW - 1) ? j + 1 : j;
                float v = pin[i * WB + j];
                v = fminf(v, pin[iu * WB + j]);
                v = fminf(v, pin[id * WB + j]);
                v = fminf(v, pin[i * WB + jl]);
                v = fminf(v, pin[i * WB + jr]);
                pout[i * WB + j] = v;
                nz |= (v != 0.0f);
            }
        }
        const int any = __syncthreads_or(nz);
        for (int i = RB - 2 + ty; i < RB + TILE + 2; i += 8) {
            const int gy = gy0 + i;
            if (gy < 0 || gy >= HW) continue;
            const int iu = (gy > 0)      ? i - 1 : i;
            const int id = (gy < HW - 1) ? i + 1 : i;
            for (int j = RB - 2 + tx; j < RB + TILE + 2; j += 32) {
                const int gx = gx0 + j;
                if (gx < 0 || gx >= HW) continue;
                const int jl = (gx > 0)      ? j - 1 : j;
                const int jr = (gx < HW - 1) ? j + 1 : j;
                float m;
                m =          pout[iu * WB + jl];
                m = fmaxf(m, pout[iu * WB + j ]);
                m = fmaxf(m, pout[iu * WB + jr]);
                m = fmaxf(m, pout[i  * WB + jl]);
                m = fmaxf(m, pout[i  * WB + j ]);
                m = fmaxf(m, pout[i  * WB + jr]);
                m = fmaxf(m, pout[id * WB + jl]);
                m = fmaxf(m, pout[id * WB + j ]);
                m = fmaxf(m, pout[id * WB + jr]);
                const float lab = pin[i * WB + j];
                const int ci = (i - (RB - 2)) * CLW + (j - (RB - 2));
                const float cl = CLB[ci];
                const float t = fmaxf(lab - m, 0.0f);
                CLB[ci] = cl + fmaxf((1.0f - cl) * t, 0.0f);
            }
        }
        __syncthreads();
        float* tmp = pin; pin = pout; pout = tmp;
        if (!any) break;
    }

    // Re-clamp CLB virtual band (edge tiles).
    if (edge) {
        if (tY == 0)
            for (int k = tid; k < 2 * CLW; k += TPB) CLB[(k / CLW) * CLW + k % CLW] = CLB[2 * CLW + k % CLW];
        if (tY == HW - TILE)
            for (int k = tid; k < 2 * CLW; k += TPB) CLB[(66 + k / CLW) * CLW + k % CLW] = CLB[65 * CLW + k % CLW];
        __syncthreads();
        if (tX == 0)
            for (int k = tid; k < 2 * CLW; k += TPB) CLB[(k >> 1) * CLW + (k & 1)] = CLB[(k >> 1) * CLW + 2];
        if (tX == HW - TILE)
            for (int k = tid; k < 2 * CLW; k += TPB) CLB[(k >> 1) * CLW + 66 + (k & 1)] = CLB[(k >> 1) * CLW + 65];
        __syncthreads();
    }

    // Separable maxpool3: Hb = hmax3 rows, D = vmax3(Hb).
    float* Hb = bufB;   // CLW x DW
    for (int c = ty; c < CLW; c += 8) {
        const float* r = CLB + c * CLW;
        float* hb = Hb + c * DW;
        for (int e = tx; e < DW; e += 32)
            hb[e] = fmaxf(fmaxf(r[e], r[e + 1]), r[e + 2]);
    }
    __syncthreads();
    float* D = bufA;    // DW x DW
    for (int d = ty; d < DW; d += 8) {
        const float* h = Hb + d * DW;
        float* dd = D + d * DW;
        for (int e = tx; e < DW; e += 32)
            dd[e] = fmaxf(fmaxf(h[e], h[e + DW]), h[e + 2 * DW]);
    }
    __syncthreads();
    if (edge) {
        if (tY == 0)          for (int e = tid; e < DW; e += TPB) D[e]           = D[DW + e];
        if (tY == HW - TILE)  for (int e = tid; e < DW; e += TPB) D[65 * DW + e] = D[64 * DW + e];
        __syncthreads();
        if (tX == 0)          for (int d = tid; d < DW; d += TPB) D[d * DW]      = D[d * DW + 1];
        if (tX == HW - TILE)  for (int d = tid; d < DW; d += TPB) D[d * DW + 65] = D[d * DW + 64];
        __syncthreads();
    }

    const float* __restrict__ xin = x + (size_t)img * HW * HW;
    const int*   __restrict__ yin = y + (size_t)(img >> 1) * HW * HW;
    const int cls = img & 1;
    float s0 = 0.0f, s1 = 0.0f;
    for (int i2 = ty; i2 < TILE; i2 += 8) {
        const int gy = tY + i2;
        const float* dc = D + (i2 + 1) * DW;
        for (int j2 = tx; j2 < TILE; j2 += 32) {
            const int e = j2 + 1;
            float v = fminf(fminf(dc[e - 1], dc[e]), dc[e + 1]);
            v = fminf(v, fminf(dc[e - DW], dc[e + DW]));
            const float w = (pipe == 0) ? ((yin[gy * HW + tX + j2] == cls) ? 1.0f : 0.0f)
                                        : xin[gy * HW + tX + j2];
            s0 += v * w;
            s1 += v;
        }
    }
    for (int o = 16; o > 0; o >>= 1) {
        s0 += __shfl_down_sync(0xffffffffu, s0, o);
        s1 += __shfl_down_sync(0xffffffffu, s1, o);
    }
    if (tx == 0) { s_r0[ty] = s0; s_r1[ty] = s1; }
    __syncthreads();
    if (tid < 8) {
        s0 = s_r0[tid]; s1 = s_r1[tid];
        for (int o = 4; o > 0; o >>= 1) {
            s0 += __shfl_down_sync(0xffu, s0, o);
            s1 += __shfl_down_sync(0xffu, s1, o);
        }
        if (tid == 0) {
            g_part[pipe][img][tileIdx][0] = s0;
            g_part[pipe][img][tileIdx][1] = s1;
        }
    }
}

// ---------------------------------------------------------------------------
__global__ void finalize_kernel(float* __restrict__ out) {
    const int t = threadIdx.x;   // 32 threads
    float dc = 0.0f;
    if (t < NIMG) {
        float np = 0.0f, dp = 0.0f, nl2 = 0.0f, dl = 0.0f;
        for (int k = 0; k < 64; k++) {
            np  += g_part[0][t][k][0];
            dp  += g_part[0][t][k][1];
            nl2 += g_part[1][t][k][0];
            dl  += g_part[1][t][k][1];
        }
        const float a = (np  + EPSF) / (dp + EPSF);
        const float b = (nl2 + EPSF) / (dl + EPSF);
        dc = 2.0f * a * b / (a + b);
    }
    for (int o = 16; o > 0; o >>= 1) dc += __shfl_down_sync(0xffffffffu, dc, o);
    if (t == 0) out[0] = -(dc * (1.0f / 16.0f));
}

// ---------------------------------------------------------------------------
extern "C" void kernel_launch(void* const* d_in, const int* in_sizes, int n_in,
                              void* d_out, int out_size) {
    const float* x = (const float*)d_in[0];
    const int*   y = (const int*)d_in[1];
    float* out = (float*)d_out;

    const int smA = (2 * WA * WA) * (int)sizeof(float);                 // 48,672 B
    const int smB = (2 * WB * WB + CLW * CLW) * (int)sizeof(float);     // 98,496 B
    cudaFuncSetAttribute(phaseA_kernel, cudaFuncAttributeMaxDynamicSharedMemorySize, smA);
    cudaFuncSetAttribute(slowB_kernel,  cudaFuncAttributeMaxDynamicSharedMemorySize, smB);

    dim3 grid(64, NIMG, 2);
    phaseA_kernel<<<grid, TPB, smA>>>(x, y);
    fastB_kernel<<<grid, TPB>>>(x, y);
    slowB_kernel<<<grid, TPB, smB>>>(x, y);
    finalize_kernel<<<1, 32>>>(out);
    (void)in_sizes; (void)n_in; (void)out_size;
}

// round 5
// speedup vs baseline: 3.2788x; 1.1013x over previous
#include <cuda_runtime.h>

#define HW    512
#define NIMG  16
#define TILE  64
#define TPB   256           // slowB
#define TPBA  512           // phaseA / fastB
#define EPSF  1e-8f

// Phase A: unified iterations 0..5 (6 iters), cl at halo 0
#define RA    7
#define WROWS 78            // valid rows/cols in phase-A buffer
#define WS    80            // padded row stride (floats) -> 512B, 16B-aligned rows
#define KA    6

// Phase B: unified iterations 6..20 (15 iters) + final pools, cl at halo 2
#define RB 18
#define WB 100
#define KB 15
#define CLW 68
#define DW  66

__device__ float g_lab[2][NIMG][HW][HW];   // lab_6 (written only where nonzero)
__device__ float g_cl [2][NIMG][HW][HW];   // cl after 6 iters
__device__ int   g_flag[2][NIMG][64];      // per-tile: lab_6 tile has nonzeros
__device__ float g_part[2][NIMG][64][2];   // per-tile partial sums

__device__ __forceinline__ int iclamp(int v) {
    return v < 0 ? 0 : (v > HW - 1 ? HW - 1 : v);
}

// ---------------------------------------------------------------------------
// Phase A: fused soft-skeleton iterations 0..5 in SMEM, float4 erosion,
// cl in registers (warp-banded, 4 rows/warp, 16 warps).
// ---------------------------------------------------------------------------
__global__ void __launch_bounds__(TPBA, 3) phaseA_kernel(const float* __restrict__ x,
                                                         const int*   __restrict__ y) {
    extern __shared__ float sm[];
    float* bufA = sm;                  // WROWS x WS
    float* bufB = sm + WROWS * WS;     // WROWS x WS

    const int tid = threadIdx.x;
    const int tx = tid & 31, ty = tid >> 5;   // ty 0..15
    const int tileIdx = blockIdx.x;
    const int img  = blockIdx.y;
    const int pipe = blockIdx.z;          // 0 = pred (x), 1 = label (one-hot of y)
    const int tY = (tileIdx >> 3) * TILE;
    const int tX = (tileIdx & 7)  * TILE;
    const int gy0 = tY - RA, gx0 = tX - RA;
    const bool edge = (tY == 0) || (tX == 0) || (tY == HW - TILE) || (tX == HW - TILE);
    const int vTop = (tY == 0)         ? 1 : 0;
    const int vBot = (tY == HW - TILE) ? 1 : 0;
    const int vL   = (tX == 0)         ? 1 : 0;
    const int vR   = (tX == HW - TILE) ? 1 : 0;

    const float* __restrict__ xin = x + (size_t)img * HW * HW;
    const int*   __restrict__ yin = y + (size_t)(img >> 1) * HW * HW;
    const int cls = img & 1;

    // Load halo region (clamped indexing == replicate padding); zero pad cols.
    if (!edge) {
        if (pipe == 0) {
            for (int i = ty; i < WROWS; i += 16) {
                const float* src = xin + (gy0 + i) * HW + gx0;
                float* dst = bufA + i * WS;
                for (int j = tx; j < WROWS; j += 32) dst[j] = src[j];
                if (tx < 2) dst[WROWS + tx] = 0.0f;
            }
        } else {
            for (int i = ty; i < WROWS; i += 16) {
                const int* src = yin + (gy0 + i) * HW + gx0;
                float* dst = bufA + i * WS;
                for (int j = tx; j < WROWS; j += 32) dst[j] = (src[j] == cls) ? 1.0f : 0.0f;
                if (tx < 2) dst[WROWS + tx] = 0.0f;
            }
        }
    } else {
        for (int i = ty; i < WROWS; i += 16) {
            const int gy = iclamp(gy0 + i);
            float* dst = bufA + i * WS;
            for (int j = tx; j < WROWS; j += 32) {
                const int gx = iclamp(gx0 + j);
                float v;
                if (pipe == 0) v = xin[gy * HW + gx];
                else           v = (yin[gy * HW + gx] == cls) ? 1.0f : 0.0f;
                dst[j] = v;
            }
            if (tx < 2) dst[WROWS + tx] = 0.0f;
        }
    }

    // cl in registers: warp ty owns rows ty*4..ty*4+3; thread cols tx, tx+32.
    float clr[2][4];
    #pragma unroll
    for (int c = 0; c < 2; c++)
        #pragma unroll
        for (int r = 0; r < 4; r++) clr[c][r] = 0.0f;

    __syncthreads();

    float* pin  = bufA;
    float* pout = bufB;

    for (int it = 0; it < KA; it++) {
        const int Hh = KA - it;               // nl halo: 6,5,4,3,2,1
        const int r0 = RA - Hh, r1 = RA + TILE + Hh;
        const int units = (r1 - r0) * 20;     // rows x 20 float4/row (full width)
        int nz = 0;
        for (int u = tid; u < units; u += TPBA) {
            const int rr  = u / 20;
            const int c4  = u - rr * 20;
            const int base = (r0 + rr) * WS + c4 * 4;
            const float4 c  = *(const float4*)(pin + base);
            const float4 up = *(const float4*)(pin + base - WS);
            const float4 dn = *(const float4*)(pin + base + WS);
            const float lft = pin[base - 1];
            const float rgt = pin[base + 4];
            float4 o;
            o.x = fminf(fminf(fminf(lft, c.y), c.x), fminf(up.x, dn.x));
            o.y = fminf(fminf(fminf(c.x, c.z), c.y), fminf(up.y, dn.y));
            o.z = fminf(fminf(fminf(c.y, c.w), c.z), fminf(up.z, dn.z));
            o.w = fminf(fminf(fminf(c.z, rgt), c.w), fminf(up.w, dn.w));
            *(float4*)(pout + base) = o;
            if (c4 >= 2 && c4 <= 17) {
                nz |= (o.x != 0.0f) | (o.y != 0.0f) | (o.z != 0.0f) | (o.w != 0.0f);
            } else {
                const int j0 = c4 * 4;
                nz |= ((o.x != 0.0f) & (j0     >= r0) & (j0     < r1));
                nz |= ((o.y != 0.0f) & (j0 + 1 >= r0) & (j0 + 1 < r1));
                nz |= ((o.z != 0.0f) & (j0 + 2 >= r0) & (j0 + 2 < r1));
                nz |= ((o.w != 0.0f) & (j0 + 3 >= r0) & (j0 + 3 < r1));
            }
        }
        const int any = __syncthreads_or(nz);

        // Re-clamp the virtual band of pout (edge tiles only) so the maxpool
        // and next erosion see exact replicate padding.
        if (edge) {
            if (vTop) for (int i = r0 + ty; i < RA; i += 16) {
                float* d = pout + i * WS; const float* s = pout + RA * WS;
                for (int j = r0 + tx; j < r1; j += 32) d[j] = s[j];
            }
            if (vBot) for (int i = RA + TILE + ty; i < r1; i += 16) {
                float* d = pout + i * WS; const float* s = pout + (RA + TILE - 1) * WS;
                for (int j = r0 + tx; j < r1; j += 32) d[j] = s[j];
            }
            __syncthreads();
            if (vL) for (int i = r0 + ty; i < r1; i += 16) {
                const float s = pout[i * WS + RA];
                for (int j = r0 + tx; j < RA; j += 32) pout[i * WS + j] = s;
            }
            if (vR) for (int i = r0 + ty; i < r1; i += 16) {
                const float s = pout[i * WS + RA + TILE - 1];
                for (int j = RA + TILE + tx; j < r1; j += 32) pout[i * WS + j] = s;
            }
            __syncthreads();
        }

        // cl += relu((1-cl)*relu(lab - maxpool3(nl))) — skip whole warp band
        // when lab is zero there (exact: lab=0 => t<=0 since m>=0).
        {
            const int rbase = RA + ty * 4;
            float labv[2][4];
            int lz = 0;
            #pragma unroll
            for (int c = 0; c < 2; c++) {
                const float* lp = pin + rbase * WS + RA + tx + c * 32;
                #pragma unroll
                for (int r = 0; r < 4; r++) {
                    labv[c][r] = lp[r * WS];
                    lz |= (labv[c][r] != 0.0f);
                }
            }
            if (__ballot_sync(0xffffffffu, lz)) {
                #pragma unroll
                for (int c = 0; c < 2; c++) {
                    const int jj = RA + tx + c * 32;
                    const float* p = pout + (rbase - 1) * WS + jj;
                    float h0 = fmaxf(fmaxf(p[-1], p[0]), p[1]); p += WS;
                    float h1 = fmaxf(fmaxf(p[-1], p[0]), p[1]); p += WS;
                    #pragma unroll
                    for (int r = 0; r < 4; r++) {
                        const float h2 = fmaxf(fmaxf(p[-1], p[0]), p[1]); p += WS;
                        const float m = fmaxf(fmaxf(h0, h1), h2);
                        const float t = labv[c][r] - m;
                        if (t > 0.0f) {
                            const float cl = clr[c][r];
                            clr[c][r] = cl + fmaxf((1.0f - cl) * t, 0.0f);
                        }
                        h0 = h1; h1 = h2;
                    }
                }
            }
        }
        __syncthreads();
        float* tmp = pin; pin = pout; pout = tmp;
        if (!any) break;   // drained over needed halo => remaining iters exact no-ops
    }

    // Store cl (registers) always; lab_6 only if tile has nonzeros; flag.
    float* __restrict__ gl = &g_lab[pipe][img][0][0];
    float* __restrict__ gc = &g_cl [pipe][img][0][0];
    int tnz = 0;
    #pragma unroll
    for (int r = 0; r < 4; r++) {
        const int row = ty * 4 + r;
        float* go = gc + (tY + row) * HW + tX;
        const float* lr = pin + (RA + row) * WS + RA;
        #pragma unroll
        for (int c = 0; c < 2; c++) {
            go[tx + c * 32] = clr[c][r];
            tnz |= (lr[tx + c * 32] != 0.0f);
        }
    }
    tnz = __syncthreads_or(tnz);
    if (tnz) {
        #pragma unroll
        for (int r = 0; r < 4; r++) {
            const int row = ty * 4 + r;
            const float* lr = pin + (RA + row) * WS + RA;
            float* go = gl + (tY + row) * HW + tX;
            go[tx]      = lr[tx];
            go[tx + 32] = lr[tx + 32];
        }
    }
    if (tid == 0) g_flag[pipe][img][tileIdx] = tnz;
}

// ---------------------------------------------------------------------------
// fastB: tiles whose 3x3 covering flags are ALL zero (lab_6 drained):
// final pools + fused reduction only.
// ---------------------------------------------------------------------------
__global__ void __launch_bounds__(TPBA) fastB_kernel(const float* __restrict__ x,
                                                     const int*   __restrict__ y) {
    __shared__ float CLB[CLW * CLW];   // cl at halo 2; reused for D (66x66, stride DW)
    __shared__ float HB[CLW * DW];     // horizontal max rows
    __shared__ float s_r0[16], s_r1[16];
    __shared__ int s_any;

    const int tid = threadIdx.x;
    const int tx = tid & 31, ty = tid >> 5;   // ty 0..15
    const int tileIdx = blockIdx.x;
    const int img  = blockIdx.y;
    const int pipe = blockIdx.z;
    const int tr = tileIdx >> 3, tc = tileIdx & 7;
    const int tY = tr * TILE, tX = tc * TILE;
    const bool edge = (tY == 0) || (tX == 0) || (tY == HW - TILE) || (tX == HW - TILE);

    if (tid == 0) {
        int a = 0;
        #pragma unroll
        for (int dr = -1; dr <= 1; dr++)
            #pragma unroll
            for (int dc2 = -1; dc2 <= 1; dc2++) {
                const int rr = tr + dr, cc = tc + dc2;
                if (rr >= 0 && rr < 8 && cc >= 0 && cc < 8)
                    a |= g_flag[pipe][img][rr * 8 + cc];
            }
        s_any = a;
    }
    __syncthreads();
    if (s_any) return;   // slowB owns this tile

    const float* __restrict__ gc = &g_cl[pipe][img][0][0];
    for (int i = ty; i < CLW; i += 16) {
        const int gy = iclamp(tY - 2 + i);
        float* d = CLB + i * CLW;
        for (int j = tx; j < CLW; j += 32) d[j] = gc[gy * HW + iclamp(tX - 2 + j)];
    }
    __syncthreads();

    // Re-clamp CLB virtual band (edge tiles) so pools read exact replicate.
    if (edge) {
        if (tY == 0)
            for (int k = tid; k < 2 * CLW; k += TPBA) CLB[(k / CLW) * CLW + k % CLW] = CLB[2 * CLW + k % CLW];
        if (tY == HW - TILE)
            for (int k = tid; k < 2 * CLW; k += TPBA) CLB[(66 + k / CLW) * CLW + k % CLW] = CLB[65 * CLW + k % CLW];
        __syncthreads();
        if (tX == 0)
            for (int k = tid; k < 2 * CLW; k += TPBA) CLB[(k >> 1) * CLW + (k & 1)] = CLB[(k >> 1) * CLW + 2];
        if (tX == HW - TILE)
            for (int k = tid; k < 2 * CLW; k += TPBA) CLB[(k >> 1) * CLW + 66 + (k & 1)] = CLB[(k >> 1) * CLW + 65];
        __syncthreads();
    }

    // Separable maxpool3: HB = hmax3 rows
    for (int c = ty; c < CLW; c += 16) {
        const float* r = CLB + c * CLW;
        float* hb = HB + c * DW;
        for (int e = tx; e < DW; e += 32)
            hb[e] = fmaxf(fmaxf(r[e], r[e + 1]), r[e + 2]);
    }
    __syncthreads();
    // D = vmax3(HB), written into CLB (free now), stride DW
    float* D = CLB;
    for (int d = ty; d < DW; d += 16) {
        const float* h = HB + d * DW;
        float* dd = D + d * DW;
        for (int e = tx; e < DW; e += 32)
            dd[e] = fmaxf(fmaxf(h[e], h[e + DW]), h[e + 2 * DW]);
    }
    __syncthreads();
    if (edge) {
        if (tY == 0)          for (int e = tid; e < DW; e += TPBA) D[e]           = D[DW + e];
        if (tY == HW - TILE)  for (int e = tid; e < DW; e += TPBA) D[65 * DW + e] = D[64 * DW + e];
        __syncthreads();
        if (tX == 0)          for (int d = tid; d < DW; d += TPBA) D[d * DW]      = D[d * DW + 1];
        if (tX == HW - TILE)  for (int d = tid; d < DW; d += TPBA) D[d * DW + 65] = D[d * DW + 64];
        __syncthreads();
    }

    // out = plus-min of D on the tile; fuse the per-(b,c) reductions.
    const float* __restrict__ xin = x + (size_t)img * HW * HW;
    const int*   __restrict__ yin = y + (size_t)(img >> 1) * HW * HW;
    const int cls = img & 1;
    float s0 = 0.0f, s1 = 0.0f;
    for (int i2 = ty; i2 < TILE; i2 += 16) {
        const int gy = tY + i2;
        const float* dc = D + (i2 + 1) * DW;
        for (int j2 = tx; j2 < TILE; j2 += 32) {
            const int e = j2 + 1;
            float v = fminf(fminf(dc[e - 1], dc[e]), dc[e + 1]);
            v = fminf(v, fminf(dc[e - DW], dc[e + DW]));
            const float w = (pipe == 0) ? ((yin[gy * HW + tX + j2] == cls) ? 1.0f : 0.0f)
                                        : xin[gy * HW + tX + j2];
            s0 += v * w;
            s1 += v;
        }
    }
    for (int o = 16; o > 0; o >>= 1) {
        s0 += __shfl_down_sync(0xffffffffu, s0, o);
        s1 += __shfl_down_sync(0xffffffffu, s1, o);
    }
    if (tx == 0) { s_r0[ty] = s0; s_r1[ty] = s1; }
    __syncthreads();
    if (tid < 16) {
        s0 = s_r0[tid]; s1 = s_r1[tid];
        for (int o = 8; o > 0; o >>= 1) {
            s0 += __shfl_down_sync(0xffffu, s0, o);
            s1 += __shfl_down_sync(0xffffu, s1, o);
        }
        if (tid == 0) {
            g_part[pipe][img][tileIdx][0] = s0;
            g_part[pipe][img][tileIdx][1] = s1;
        }
    }
}

// ---------------------------------------------------------------------------
// slowB: tiles with any covering flag set: iterations 6..20 + pools +
// reduction. Exits immediately otherwise (expected for all tiles).
// ---------------------------------------------------------------------------
__global__ void __launch_bounds__(TPB) slowB_kernel(const float* __restrict__ x,
                                                    const int*   __restrict__ y) {
    extern __shared__ float sm[];
    float* bufA = sm;                 // WB*WB (lab ping; reused for D 66x66)
    float* bufB = sm + WB * WB;       // WB*WB (lab pong; reused for Hb 68x66)
    float* CLB  = sm + 2 * WB * WB;   // CLW*CLW (cl at halo 2)
    __shared__ float s_r0[8], s_r1[8];
    __shared__ int s_flags[9];

    const int tid = threadIdx.x;
    const int tx = tid & 31, ty = tid >> 5;
    const int tileIdx = blockIdx.x;
    const int img  = blockIdx.y;
    const int pipe = blockIdx.z;
    const int tr = tileIdx >> 3, tc = tileIdx & 7;
    const int tY = tr * TILE, tX = tc * TILE;
    const int gy0 = tY - RB, gx0 = tX - RB;
    const bool edge = (tY == 0) || (tX == 0) || (tY == HW - TILE) || (tX == HW - TILE);

    if (tid < 9) {
        const int rr = tr + tid / 3 - 1, cc = tc + tid % 3 - 1;
        int f = 0;
        if (rr >= 0 && rr < 8 && cc >= 0 && cc < 8) f = g_flag[pipe][img][rr * 8 + cc];
        s_flags[tid] = f;
    }
    __syncthreads();
    int anyLab = 0;
    #pragma unroll
    for (int k = 0; k < 9; k++) anyLab |= s_flags[k];
    if (!anyLab) return;   // fastB owns this tile

    const float* __restrict__ gl = &g_lab[pipe][img][0][0];
    const float* __restrict__ gc = &g_cl [pipe][img][0][0];

    for (int i = ty; i < CLW; i += 8) {
        const int gy = iclamp(tY - 2 + i);
        float* d = CLB + i * CLW;
        for (int j = tx; j < CLW; j += 32) d[j] = gc[gy * HW + iclamp(tX - 2 + j)];
    }
    for (int i = ty; i < WB; i += 8) {
        const int gy = iclamp(gy0 + i);
        const int fr = (gy >> 6) - (tr - 1);
        for (int j = tx; j < WB; j += 32) {
            const int gx = iclamp(gx0 + j);
            const int fc = (gx >> 6) - (tc - 1);
            bufA[i * WB + j] = s_flags[fr * 3 + fc] ? gl[gy * HW + gx] : 0.0f;
        }
    }
    __syncthreads();

    float* pin  = bufA;
    float* pout = bufB;
    for (int it = 0; it < KB; it++) {
        int Hh = 17 - it; if (Hh < 3) Hh = 3;
        const int r0 = RB - Hh, r1 = RB + TILE + Hh;
        int nz = 0;
        for (int i = r0 + ty; i < r1; i += 8) {
            const int gy = gy0 + i;
            if (gy < 0 || gy >= HW) continue;
            const int iu = (gy > 0)      ? i - 1 : i;
            const int id = (gy < HW - 1) ? i + 1 : i;
            for (int j = r0 + tx; j < r1; j += 32) {
                const int gx = gx0 + j;
                if (gx < 0 || gx >= HW) continue;
                const int jl = (gx > 0)      ? j - 1 : j;
                const int jr = (gx < HW - 1) ? j + 1 : j;
                float v = pin[i * WB + j];
                v = fminf(v, pin[iu * WB + j]);
                v = fminf(v, pin[id * WB + j]);
                v = fminf(v, pin[i * WB + jl]);
                v = fminf(v, pin[i * WB + jr]);
                pout[i * WB + j] = v;
                nz |= (v != 0.0f);
            }
        }
        const int any = __syncthreads_or(nz);
        for (int i = RB - 2 + ty; i < RB + TILE + 2; i += 8) {
            const int gy = gy0 + i;
            if (gy < 0 || gy >= HW) continue;
            const int iu = (gy > 0)      ? i - 1 : i;
            const int id = (gy < HW - 1) ? i + 1 : i;
            for (int j = RB - 2 + tx; j < RB + TILE + 2; j += 32) {
                const int gx = gx0 + j;
                if (gx < 0 || gx >= HW) continue;
                const int jl = (gx > 0)      ? j - 1 : j;
                const int jr = (gx < HW - 1) ? j + 1 : j;
                float m;
                m =          pout[iu * WB + jl];
                m = fmaxf(m, pout[iu * WB + j ]);
                m = fmaxf(m, pout[iu * WB + jr]);
                m = fmaxf(m, pout[i  * WB + jl]);
                m = fmaxf(m, pout[i  * WB + j ]);
                m = fmaxf(m, pout[i  * WB + jr]);
                m = fmaxf(m, pout[id * WB + jl]);
                m = fmaxf(m, pout[id * WB + j ]);
                m = fmaxf(m, pout[id * WB + jr]);
                const float lab = pin[i * WB + j];
                const int ci = (i - (RB - 2)) * CLW + (j - (RB - 2));
                const float cl = CLB[ci];
                const float t = fmaxf(lab - m, 0.0f);
                CLB[ci] = cl + fmaxf((1.0f - cl) * t, 0.0f);
            }
        }
        __syncthreads();
        float* tmp = pin; pin = pout; pout = tmp;
        if (!any) break;
    }

    if (edge) {
        if (tY == 0)
            for (int k = tid; k < 2 * CLW; k += TPB) CLB[(k / CLW) * CLW + k % CLW] = CLB[2 * CLW + k % CLW];
        if (tY == HW - TILE)
            for (int k = tid; k < 2 * CLW; k += TPB) CLB[(66 + k / CLW) * CLW + k % CLW] = CLB[65 * CLW + k % CLW];
        __syncthreads();
        if (tX == 0)
            for (int k = tid; k < 2 * CLW; k += TPB) CLB[(k >> 1) * CLW + (k & 1)] = CLB[(k >> 1) * CLW + 2];
        if (tX == HW - TILE)
            for (int k = tid; k < 2 * CLW; k += TPB) CLB[(k >> 1) * CLW + 66 + (k & 1)] = CLB[(k >> 1) * CLW + 65];
        __syncthreads();
    }

    float* Hb = bufB;   // CLW x DW
    for (int c = ty; c < CLW; c += 8) {
        const float* r = CLB + c * CLW;
        float* hb = Hb + c * DW;
        for (int e = tx; e < DW; e += 32)
            hb[e] = fmaxf(fmaxf(r[e], r[e + 1]), r[e + 2]);
    }
    __syncthreads();
    float* D = bufA;    // DW x DW
    for (int d = ty; d < DW; d += 8) {
        const float* h = Hb + d * DW;
        float* dd = D + d * DW;
        for (int e = tx; e < DW; e += 32)
            dd[e] = fmaxf(fmaxf(h[e], h[e + DW]), h[e + 2 * DW]);
    }
    __syncthreads();
    if (edge) {
        if (tY == 0)          for (int e = tid; e < DW; e += TPB) D[e]           = D[DW + e];
        if (tY == HW - TILE)  for (int e = tid; e < DW; e += TPB) D[65 * DW + e] = D[64 * DW + e];
        __syncthreads();
        if (tX == 0)          for (int d = tid; d < DW; d += TPB) D[d * DW]      = D[d * DW + 1];
        if (tX == HW - TILE)  for (int d = tid; d < DW; d += TPB) D[d * DW + 65] = D[d * DW + 64];
        __syncthreads();
    }

    const float* __restrict__ xin = x + (size_t)img * HW * HW;
    const int*   __restrict__ yin = y + (size_t)(img >> 1) * HW * HW;
    const int cls = img & 1;
    float s0 = 0.0f, s1 = 0.0f;
    for (int i2 = ty; i2 < TILE; i2 += 8) {
        const int gy = tY + i2;
        const float* dc = D + (i2 + 1) * DW;
        for (int j2 = tx; j2 < TILE; j2 += 32) {
            const int e = j2 + 1;
            float v = fminf(fminf(dc[e - 1], dc[e]), dc[e + 1]);
            v = fminf(v, fminf(dc[e - DW], dc[e + DW]));
            const float w = (pipe == 0) ? ((yin[gy * HW + tX + j2] == cls) ? 1.0f : 0.0f)
                                        : xin[gy * HW + tX + j2];
            s0 += v * w;
            s1 += v;
        }
    }
    for (int o = 16; o > 0; o >>= 1) {
        s0 += __shfl_down_sync(0xffffffffu, s0, o);
        s1 += __shfl_down_sync(0xffffffffu, s1, o);
    }
    if (tx == 0) { s_r0[ty] = s0; s_r1[ty] = s1; }
    __syncthreads();
    if (tid < 8) {
        s0 = s_r0[tid]; s1 = s_r1[tid];
        for (int o = 4; o > 0; o >>= 1) {
            s0 += __shfl_down_sync(0xffu, s0, o);
            s1 += __shfl_down_sync(0xffu, s1, o);
        }
        if (tid == 0) {
            g_part[pipe][img][tileIdx][0] = s0;
            g_part[pipe][img][tileIdx][1] = s1;
        }
    }
}

// ---------------------------------------------------------------------------
__global__ void finalize_kernel(float* __restrict__ out) {
    const int t = threadIdx.x;   // 32 threads
    float dc = 0.0f;
    if (t < NIMG) {
        float np = 0.0f, dp = 0.0f, nl2 = 0.0f, dl = 0.0f;
        for (int k = 0; k < 64; k++) {
            np  += g_part[0][t][k][0];
            dp  += g_part[0][t][k][1];
            nl2 += g_part[1][t][k][0];
            dl  += g_part[1][t][k][1];
        }
        const float a = (np  + EPSF) / (dp + EPSF);
        const float b = (nl2 + EPSF) / (dl + EPSF);
        dc = 2.0f * a * b / (a + b);
    }
    for (int o = 16; o > 0; o >>= 1) dc += __shfl_down_sync(0xffffffffu, dc, o);
    if (t == 0) out[0] = -(dc * (1.0f / 16.0f));
}

// ---------------------------------------------------------------------------
extern "C" void kernel_launch(void* const* d_in, const int* in_sizes, int n_in,
                              void* d_out, int out_size) {
    const float* x = (const float*)d_in[0];
    const int*   y = (const int*)d_in[1];
    float* out = (float*)d_out;

    const int smA = (2 * WROWS * WS) * (int)sizeof(float);              // 49,920 B
    const int smB = (2 * WB * WB + CLW * CLW) * (int)sizeof(float);     // 98,496 B
    cudaFuncSetAttribute(phaseA_kernel, cudaFuncAttributeMaxDynamicSharedMemorySize, smA);
    cudaFuncSetAttribute(slowB_kernel,  cudaFuncAttributeMaxDynamicSharedMemorySize, smB);

    dim3 grid(64, NIMG, 2);
    phaseA_kernel<<<grid, TPBA, smA>>>(x, y);
    fastB_kernel<<<grid, TPBA>>>(x, y);
    slowB_kernel<<<grid, TPB, smB>>>(x, y);
    finalize_kernel<<<1, 32>>>(out);
    (void)in_sizes; (void)n_in; (void)out_size;
}